// round 6
// baseline (speedup 1.0000x reference)
#include <cuda_runtime.h>
#include <cstdint>

#define EMB 64
#define MAXN 200000
#define MAXB 16384

// Scratch (static __device__ globals: allocation-free).
__device__ float  g_hacc[2][(size_t)MAXN * EMB];    // sum of exp(e)*src_feat per dst node
__device__ float2 g_ds[2][MAXN];                    // .x = s_dst score, .y = sum of exp(e)
__device__ unsigned char g_flag[2][MAXN];           // 1 if node is in the batch

// ---------------------------------------------------------------------------
// K1: per (side, batch element): mark flag, zero accumulators, compute s_dst.
// One warp per (side, b). Duplicate ids write identical values (benign).
// ---------------------------------------------------------------------------
__global__ void __launch_bounds__(256)
prep_kernel(const float* __restrict__ utab, const float* __restrict__ itab,
            const float* __restrict__ Wa_u, const float* __restrict__ Wa_i,
            const int* __restrict__ uids, const int* __restrict__ iids, int B)
{
    int gw = (blockIdx.x * blockDim.x + threadIdx.x) >> 5;
    int lane = threadIdx.x & 31;
    if (gw >= 2 * B) return;
    int side = gw >= B ? 1 : 0;
    int b = side ? gw - B : gw;
    int id = side ? iids[b] : uids[b];
    const float* tab = side ? itab : utab;
    const float* wa = (side ? Wa_i : Wa_u) + EMB;   // dst half of attention vector

    float2 v = *(const float2*)(tab + (size_t)id * EMB + 2 * lane);
    float p = v.x * wa[2 * lane] + v.y * wa[2 * lane + 1];
    #pragma unroll
    for (int o = 16; o; o >>= 1) p += __shfl_xor_sync(0xffffffffu, p, o);

    *(float2*)(&g_hacc[side][(size_t)id * EMB + 2 * lane]) = make_float2(0.f, 0.f);
    if (lane == 0) {
        g_ds[side][id] = make_float2(p, 0.f);
        g_flag[side][id] = 1;
    }
}

// ---------------------------------------------------------------------------
// K2: fused edge pass. Half-warp (16 lanes) per flagged edge; two flagged
// edges per warp iteration. float4 gather + red.global.add.v4.f32 scatter
// (16 lane-ops/edge instead of 32).
// No segment-max subtraction: logit std ~0.1, constant factor cancels.
// ---------------------------------------------------------------------------
__global__ void __launch_bounds__(256)
edge_kernel(const float* __restrict__ utab, const float* __restrict__ itab,
            const float* __restrict__ Wa_u, const float* __restrict__ Wa_i,
            const int* __restrict__ src_iu, const int* __restrict__ dst_iu,
            const int* __restrict__ src_ui, const int* __restrict__ dst_ui,
            int E)
{
    int side = blockIdx.y;
    const float* stab = side ? utab : itab;         // source-node feature table
    const float* wa = side ? Wa_i : Wa_u;           // src half [0:64)
    const int* src = side ? src_ui : src_iu;
    const int* dst = side ? dst_ui : dst_iu;
    const unsigned char* flag = g_flag[side];

    int lane = threadIdx.x & 31;
    int half = lane >> 4, hl = lane & 15;
    float4 w4 = *(const float4*)(wa + 4 * hl);

    int warp = (blockIdx.x * blockDim.x + threadIdx.x) >> 5;
    int idx = warp * 32 + lane;

    int d = 0, s = 0, f = 0;
    if (idx < E) {
        d = dst[idx];
        f = flag[d];
        s = src[idx];
    }
    unsigned m = __ballot_sync(0xffffffffu, f);

    while (m) {
        int j0 = __ffs(m) - 1; m &= m - 1;
        int j1 = -1;
        if (m) { j1 = __ffs(m) - 1; m &= m - 1; }
        int j = half ? j1 : j0;
        bool act = (j >= 0);
        int jl = act ? j : j0;
        int ds = __shfl_sync(0xffffffffu, d, jl);
        int ss = __shfl_sync(0xffffffffu, s, jl);

        // Half-warp gather of the 64-float source row (16 lanes x float4).
        float4 v = *(const float4*)(stab + (size_t)ss * EMB + 4 * hl);
        float p = v.x * w4.x + v.y * w4.y + v.z * w4.z + v.w * w4.w;
        #pragma unroll
        for (int o = 8; o; o >>= 1) p += __shfl_xor_sync(0xffffffffu, p, o);

        float e = p + g_ds[side][ds].x;
        e = e >= 0.f ? e : 0.01f * e;          // leaky_relu(., 0.01)
        float ex = __expf(e);

        if (act) {
            if (hl == 0) atomicAdd(&g_ds[side][ds].y, ex);
            float* hp = &g_hacc[side][(size_t)ds * EMB + 4 * hl];
            asm volatile("red.global.add.v4.f32 [%0], {%1, %2, %3, %4};"
                         :: "l"(hp), "f"(v.x * ex), "f"(v.y * ex),
                            "f"(v.z * ex), "f"(v.w * ex) : "memory");
        }
    }
}

// ---------------------------------------------------------------------------
// K3: fully fused MLP. One block = 32 batch rows of one side.
//   ibuf[32][132]: cat(emb, h) inputs; overwritten in-place by z.
//   wbuf[64][68]:  one transposed weight tile, reused for Ws, Wn, Wfc x2.
// All intermediate z stays in smem (no global round-trip).
// 256 threads as tx(16 out-col groups of 4) x ty(16 row groups of 2).
// ---------------------------------------------------------------------------
__global__ void __launch_bounds__(256)
mlp_fused_kernel(const float* __restrict__ utab, const float* __restrict__ itab,
                 const float* __restrict__ Ws_u, const float* __restrict__ bs_u,
                 const float* __restrict__ Ws_i, const float* __restrict__ bs_i,
                 const float* __restrict__ Wn_u, const float* __restrict__ bn_u,
                 const float* __restrict__ Wn_i, const float* __restrict__ bn_i,
                 const float* __restrict__ Wfc_u, const float* __restrict__ Wfc_i,
                 const int* __restrict__ uids, const int* __restrict__ iids,
                 float* __restrict__ out, int B)
{
    int side = blockIdx.y;
    const float* tab = side ? itab : utab;
    const float* Ws = side ? Ws_i : Ws_u;
    const float* Wn = side ? Wn_i : Wn_u;
    const float* Wfc = side ? Wfc_i : Wfc_u;
    const float* bsv = side ? bs_i : bs_u;
    const float* bnv = side ? bn_i : bn_u;
    const int* ids = side ? iids : uids;

    __shared__ float ibuf[32 * 132];   // [row][k 0..127], float4-aligned stride
    __shared__ float wbuf[64 * 68];    // [k][out], float4-aligned stride
    __shared__ int   ids_s[32];
    __shared__ float rden_s[32];

    int tid = threadIdx.x;
    int tx = tid & 15, ty = tid >> 4;

    if (tid < 32) {
        int b = blockIdx.x * 32 + tid; if (b >= B) b = B - 1;
        int id = ids[b];
        ids_s[tid] = id;
        float den = g_ds[side][id].y;
        rden_s[tid] = den > 0.f ? 1.f / den : 0.f;   // empty segment -> h = 0
    }
    // Load Ws transposed while ids land.
    for (int t = tid; t < 4096; t += 256) {
        int o = t >> 6, k = t & 63;
        wbuf[k * 68 + o] = Ws[t];
    }
    __syncthreads();
    // Gather inputs: 32 rows x 32 float4 groups (emb in cols 0..63, h in 64..127).
    for (int t = tid; t < 1024; t += 256) {
        int row = t >> 5, g = t & 31, k0 = g * 4;
        int id = ids_s[row];
        float4 v;
        if (g < 16) {
            v = *(const float4*)&tab[(size_t)id * EMB + k0];
        } else {
            v = *(const float4*)&g_hacc[side][(size_t)id * EMB + (k0 - 64)];
            float r = rden_s[row];
            v.x *= r; v.y *= r; v.z *= r; v.w *= r;
        }
        *(float4*)&ibuf[row * 132 + k0] = v;
    }
    __syncthreads();

    // Stage 1a: accS = Ws @ emb
    float accS[2][4] = {}, accN[2][4] = {};
    #pragma unroll 8
    for (int k = 0; k < 64; k++) {
        float4 w = *(const float4*)&wbuf[k * 68 + 4 * tx];
        #pragma unroll
        for (int r = 0; r < 2; r++) {
            float a = ibuf[(2 * ty + r) * 132 + k];
            accS[r][0] += a * w.x; accS[r][1] += a * w.y;
            accS[r][2] += a * w.z; accS[r][3] += a * w.w;
        }
    }
    __syncthreads();
    // Stage 1b: load Wn, accN = Wn @ h
    for (int t = tid; t < 4096; t += 256) {
        int o = t >> 6, k = t & 63;
        wbuf[k * 68 + o] = Wn[t];
    }
    __syncthreads();
    #pragma unroll 8
    for (int k = 0; k < 64; k++) {
        float4 w = *(const float4*)&wbuf[k * 68 + 4 * tx];
        #pragma unroll
        for (int r = 0; r < 2; r++) {
            float a = ibuf[(2 * ty + r) * 132 + 64 + k];
            accN[r][0] += a * w.x; accN[r][1] += a * w.y;
            accN[r][2] += a * w.z; accN[r][3] += a * w.w;
        }
    }
    __syncthreads();   // all input reads done; safe to overwrite ibuf with z

    float4 bS = *(const float4*)&bsv[4 * tx];
    float4 bN = *(const float4*)&bnv[4 * tx];
    #pragma unroll
    for (int r = 0; r < 2; r++) {
        int row = 2 * ty + r;
        float4 zs, zn;
        zs.x = fmaxf(accS[r][0] + bS.x, 0.f); zs.y = fmaxf(accS[r][1] + bS.y, 0.f);
        zs.z = fmaxf(accS[r][2] + bS.z, 0.f); zs.w = fmaxf(accS[r][3] + bS.w, 0.f);
        zn.x = fmaxf(accN[r][0] + bN.x, 0.f); zn.y = fmaxf(accN[r][1] + bN.y, 0.f);
        zn.z = fmaxf(accN[r][2] + bN.z, 0.f); zn.w = fmaxf(accN[r][3] + bN.w, 0.f);
        *(float4*)&ibuf[row * 132 + 4 * tx] = zs;
        *(float4*)&ibuf[row * 132 + 64 + 4 * tx] = zn;
    }
    __syncthreads();

    // Stage 2: out = relu(Wfc @ z), k = 128 in two 64-wide chunks.
    float acc2[2][4] = {};
    #pragma unroll
    for (int kc = 0; kc < 2; kc++) {
        for (int t = tid; t < 4096; t += 256) {
            int o = t >> 6, k = t & 63;
            wbuf[k * 68 + o] = Wfc[o * 128 + kc * 64 + k];
        }
        __syncthreads();
        #pragma unroll 8
        for (int k = 0; k < 64; k++) {
            float4 w = *(const float4*)&wbuf[k * 68 + 4 * tx];
            #pragma unroll
            for (int r = 0; r < 2; r++) {
                float a = ibuf[(2 * ty + r) * 132 + kc * 64 + k];
                acc2[r][0] += a * w.x; acc2[r][1] += a * w.y;
                acc2[r][2] += a * w.z; acc2[r][3] += a * w.w;
            }
        }
        __syncthreads();
    }

    #pragma unroll
    for (int r = 0; r < 2; r++) {
        int b = blockIdx.x * 32 + 2 * ty + r;
        if (b >= B) continue;
        float4 o;
        o.x = fmaxf(acc2[r][0], 0.f);
        o.y = fmaxf(acc2[r][1], 0.f);
        o.z = fmaxf(acc2[r][2], 0.f);
        o.w = fmaxf(acc2[r][3], 0.f);
        *(float4*)&out[(size_t)b * 2 * EMB + side * EMB + 4 * tx] = o;
    }
}

// ---------------------------------------------------------------------------
extern "C" void kernel_launch(void* const* d_in, const int* in_sizes, int n_in,
                              void* d_out, int out_size)
{
    const float* user_emb = (const float*)d_in[0];
    const float* item_emb = (const float*)d_in[1];
    const float* Wa_u = (const float*)d_in[2];
    const float* Wa_i = (const float*)d_in[3];
    const float* Wfc_u = (const float*)d_in[4];
    const float* Wfc_i = (const float*)d_in[5];
    const float* Ws_u = (const float*)d_in[6];
    const float* bs_u = (const float*)d_in[7];
    const float* Ws_i = (const float*)d_in[8];
    const float* bs_i = (const float*)d_in[9];
    const float* Wn_u = (const float*)d_in[10];
    const float* bn_u = (const float*)d_in[11];
    const float* Wn_i = (const float*)d_in[12];
    const float* bn_i = (const float*)d_in[13];
    const int* u      = (const int*)d_in[14];
    const int* ii     = (const int*)d_in[15];
    const int* src_iu = (const int*)d_in[16];
    const int* dst_iu = (const int*)d_in[17];
    const int* src_ui = (const int*)d_in[18];
    const int* dst_ui = (const int*)d_in[19];
    int B = in_sizes[14];
    int E = in_sizes[16];
    float* out = (float*)d_out;

    {   // K1: mark + zero + dst scores. One warp per (side, b).
        int threads = 256;
        int blocks = (2 * B * 32 + threads - 1) / threads;
        prep_kernel<<<blocks, threads>>>(user_emb, item_emb, Wa_u, Wa_i, u, ii, B);
    }
    {   // K2: fused filtered edge pass, both sides concurrent via gridDim.y.
        int threads = 256;
        int blocks = (E + 8 * 32 - 1) / (8 * 32);
        dim3 g(blocks, 2);
        edge_kernel<<<g, threads>>>(user_emb, item_emb, Wa_u, Wa_i,
                                    src_iu, dst_iu, src_ui, dst_ui, E);
    }
    {   // K3: fully fused MLP (no z round-trip).
        dim3 g((B + 31) / 32, 2);
        mlp_fused_kernel<<<g, 256>>>(user_emb, item_emb, Ws_u, bs_u, Ws_i, bs_i,
                                     Wn_u, bn_u, Wn_i, bn_i, Wfc_u, Wfc_i,
                                     u, ii, out, B);
    }
}

// round 8
// speedup vs baseline: 1.0539x; 1.0539x over previous
#include <cuda_runtime.h>
#include <cstdint>

#define EMB 64
#define MAXN 200000
#define MAXB 16384

// Scratch (static __device__ globals: allocation-free).
__device__ float  g_hacc[2][(size_t)MAXN * EMB];    // sum of exp(e)*src_feat per dst node
__device__ float2 g_ds[2][MAXN];                    // .x = s_dst score, .y = sum of exp(e)
__device__ unsigned char g_flag[2][MAXN];           // 1 if node is in the batch

// ---------------------------------------------------------------------------
// K1: per (side, batch element): mark flag, zero accumulators, compute s_dst.
// One warp per (side, b). Duplicate ids write identical values (benign).
// ---------------------------------------------------------------------------
__global__ void __launch_bounds__(256)
prep_kernel(const float* __restrict__ utab, const float* __restrict__ itab,
            const float* __restrict__ Wa_u, const float* __restrict__ Wa_i,
            const int* __restrict__ uids, const int* __restrict__ iids, int B)
{
    int gw = (blockIdx.x * blockDim.x + threadIdx.x) >> 5;
    int lane = threadIdx.x & 31;
    if (gw >= 2 * B) return;
    int side = gw >= B ? 1 : 0;
    int b = side ? gw - B : gw;
    int id = side ? iids[b] : uids[b];
    const float* tab = side ? itab : utab;
    const float* wa = (side ? Wa_i : Wa_u) + EMB;   // dst half of attention vector

    float2 v = *(const float2*)(tab + (size_t)id * EMB + 2 * lane);
    float p = v.x * wa[2 * lane] + v.y * wa[2 * lane + 1];
    #pragma unroll
    for (int o = 16; o; o >>= 1) p += __shfl_xor_sync(0xffffffffu, p, o);

    *(float2*)(&g_hacc[side][(size_t)id * EMB + 2 * lane]) = make_float2(0.f, 0.f);
    if (lane == 0) {
        g_ds[side][id] = make_float2(p, 0.f);
        g_flag[side][id] = 1;
    }
}

// ---------------------------------------------------------------------------
// K2: single fused edge pass (filter + score + exp + weighted scatter).
// 32 edges per warp; flagged edges (~8%) processed warp-cooperatively.
// No segment-max subtraction: logit std ~0.1, constant factor cancels in alpha.
// Scatter uses red.global.add.v2.f32 (sm_90+). (Exact R5 configuration.)
// ---------------------------------------------------------------------------
__global__ void __launch_bounds__(256)
edge_kernel(const float* __restrict__ utab, const float* __restrict__ itab,
            const float* __restrict__ Wa_u, const float* __restrict__ Wa_i,
            const int* __restrict__ src_iu, const int* __restrict__ dst_iu,
            const int* __restrict__ src_ui, const int* __restrict__ dst_ui,
            int E)
{
    int side = blockIdx.y;
    const float* stab = side ? utab : itab;         // source-node feature table
    const float* wa = side ? Wa_i : Wa_u;           // src half [0:64)
    const int* src = side ? src_ui : src_iu;
    const int* dst = side ? dst_ui : dst_iu;
    const unsigned char* flag = g_flag[side];

    int lane = threadIdx.x & 31;
    float wx = wa[2 * lane], wy = wa[2 * lane + 1];

    int warp = (blockIdx.x * blockDim.x + threadIdx.x) >> 5;
    int idx = warp * 32 + lane;

    int d = 0, s = 0, f = 0;
    if (idx < E) {
        d = dst[idx];
        f = flag[d];
        s = src[idx];
    }
    unsigned m = __ballot_sync(0xffffffffu, f);

    while (m) {
        int j = __ffs(m) - 1; m &= m - 1;
        int ds = __shfl_sync(0xffffffffu, d, j);
        int ss = __shfl_sync(0xffffffffu, s, j);

        // Warp-cooperative gather of the 64-float source row (256B, coalesced).
        float2 v = *(const float2*)(stab + (size_t)ss * EMB + 2 * lane);
        float p = v.x * wx + v.y * wy;
        #pragma unroll
        for (int o = 16; o; o >>= 1) p += __shfl_xor_sync(0xffffffffu, p, o);

        float e = p + g_ds[side][ds].x;
        e = e >= 0.f ? e : 0.01f * e;          // leaky_relu(., 0.01)
        float ex = __expf(e);

        if (lane == 0) atomicAdd(&g_ds[side][ds].y, ex);
        float* hp = &g_hacc[side][(size_t)ds * EMB + 2 * lane];
        asm volatile("red.global.add.v2.f32 [%0], {%1, %2};"
                     :: "l"(hp), "f"(v.x * ex), "f"(v.y * ex) : "memory");
    }
}

// ---------------------------------------------------------------------------
// K3: fully fused MLP. One block = 32 batch rows of one side, 128 threads.
//   ibuf[32][132]: cat(emb, h) inputs; overwritten in-place by z.
//   wbuf[64][68]:  one transposed weight tile, reused for Ws, Wn, Wfc x2.
// Thread tile 4 rows x 4 cols: per k, 1 LDS.128 + 4 broadcast LDS / 16 FFMA.
// ---------------------------------------------------------------------------
__global__ void __launch_bounds__(128)
mlp_fused_kernel(const float* __restrict__ utab, const float* __restrict__ itab,
                 const float* __restrict__ Ws_u, const float* __restrict__ bs_u,
                 const float* __restrict__ Ws_i, const float* __restrict__ bs_i,
                 const float* __restrict__ Wn_u, const float* __restrict__ bn_u,
                 const float* __restrict__ Wn_i, const float* __restrict__ bn_i,
                 const float* __restrict__ Wfc_u, const float* __restrict__ Wfc_i,
                 const int* __restrict__ uids, const int* __restrict__ iids,
                 float* __restrict__ out, int B)
{
    int side = blockIdx.y;
    const float* tab = side ? itab : utab;
    const float* Ws = side ? Ws_i : Ws_u;
    const float* Wn = side ? Wn_i : Wn_u;
    const float* Wfc = side ? Wfc_i : Wfc_u;
    const float* bsv = side ? bs_i : bs_u;
    const float* bnv = side ? bn_i : bn_u;
    const int* ids = side ? iids : uids;

    __shared__ float ibuf[32 * 132];   // [row][k 0..127], float4-aligned stride
    __shared__ float wbuf[64 * 68];    // [k][out], float4-aligned stride
    __shared__ int   ids_s[32];
    __shared__ float rden_s[32];

    int tid = threadIdx.x;
    int tx = tid & 15, ty = tid >> 4;  // tx: 16 col-groups of 4; ty: 8 row-groups of 4

    if (tid < 32) {
        int b = blockIdx.x * 32 + tid; if (b >= B) b = B - 1;
        int id = ids[b];
        ids_s[tid] = id;
        float den = g_ds[side][id].y;
        rden_s[tid] = den > 0.f ? 1.f / den : 0.f;   // empty segment -> h = 0
    }
    // Load Ws transposed (float4 global reads, 4 scalar smem stores).
    for (int t = tid; t < 1024; t += 128) {
        int o = t >> 4, kg = t & 15;
        float4 w = *(const float4*)&Ws[o * 64 + 4 * kg];
        wbuf[(4 * kg + 0) * 68 + o] = w.x;
        wbuf[(4 * kg + 1) * 68 + o] = w.y;
        wbuf[(4 * kg + 2) * 68 + o] = w.z;
        wbuf[(4 * kg + 3) * 68 + o] = w.w;
    }
    __syncthreads();
    // Gather inputs: 32 rows x 32 float4 groups (emb in cols 0..63, h in 64..127).
    for (int t = tid; t < 1024; t += 128) {
        int row = t >> 5, g = t & 31, k0 = g * 4;
        int id = ids_s[row];
        float4 v;
        if (g < 16) {
            v = *(const float4*)&tab[(size_t)id * EMB + k0];
        } else {
            v = *(const float4*)&g_hacc[side][(size_t)id * EMB + (k0 - 64)];
            float r = rden_s[row];
            v.x *= r; v.y *= r; v.z *= r; v.w *= r;
        }
        *(float4*)&ibuf[row * 132 + k0] = v;
    }
    __syncthreads();

    // Stage 1a: accS = Ws @ emb
    float accS[4][4] = {}, accN[4][4] = {};
    #pragma unroll 8
    for (int k = 0; k < 64; k++) {
        float4 w = *(const float4*)&wbuf[k * 68 + 4 * tx];
        #pragma unroll
        for (int r = 0; r < 4; r++) {
            float a = ibuf[(4 * ty + r) * 132 + k];
            accS[r][0] += a * w.x; accS[r][1] += a * w.y;
            accS[r][2] += a * w.z; accS[r][3] += a * w.w;
        }
    }
    __syncthreads();
    // Stage 1b: load Wn, accN = Wn @ h
    for (int t = tid; t < 1024; t += 128) {
        int o = t >> 4, kg = t & 15;
        float4 w = *(const float4*)&Wn[o * 64 + 4 * kg];
        wbuf[(4 * kg + 0) * 68 + o] = w.x;
        wbuf[(4 * kg + 1) * 68 + o] = w.y;
        wbuf[(4 * kg + 2) * 68 + o] = w.z;
        wbuf[(4 * kg + 3) * 68 + o] = w.w;
    }
    __syncthreads();
    #pragma unroll 8
    for (int k = 0; k < 64; k++) {
        float4 w = *(const float4*)&wbuf[k * 68 + 4 * tx];
        #pragma unroll
        for (int r = 0; r < 4; r++) {
            float a = ibuf[(4 * ty + r) * 132 + 64 + k];
            accN[r][0] += a * w.x; accN[r][1] += a * w.y;
            accN[r][2] += a * w.z; accN[r][3] += a * w.w;
        }
    }
    __syncthreads();   // all input reads done; safe to overwrite ibuf with z

    float4 bS = *(const float4*)&bsv[4 * tx];
    float4 bN = *(const float4*)&bnv[4 * tx];
    #pragma unroll
    for (int r = 0; r < 4; r++) {
        int row = 4 * ty + r;
        float4 zs, zn;
        zs.x = fmaxf(accS[r][0] + bS.x, 0.f); zs.y = fmaxf(accS[r][1] + bS.y, 0.f);
        zs.z = fmaxf(accS[r][2] + bS.z, 0.f); zs.w = fmaxf(accS[r][3] + bS.w, 0.f);
        zn.x = fmaxf(accN[r][0] + bN.x, 0.f); zn.y = fmaxf(accN[r][1] + bN.y, 0.f);
        zn.z = fmaxf(accN[r][2] + bN.z, 0.f); zn.w = fmaxf(accN[r][3] + bN.w, 0.f);
        *(float4*)&ibuf[row * 132 + 4 * tx] = zs;
        *(float4*)&ibuf[row * 132 + 64 + 4 * tx] = zn;
    }
    __syncthreads();

    // Stage 2: out = relu(Wfc @ z), k = 128 in two 64-wide chunks.
    float acc2[4][4] = {};
    #pragma unroll
    for (int kc = 0; kc < 2; kc++) {
        for (int t = tid; t < 1024; t += 128) {
            int o = t >> 4, kg = t & 15;
            float4 w = *(const float4*)&Wfc[o * 128 + kc * 64 + 4 * kg];
            wbuf[(4 * kg + 0) * 68 + o] = w.x;
            wbuf[(4 * kg + 1) * 68 + o] = w.y;
            wbuf[(4 * kg + 2) * 68 + o] = w.z;
            wbuf[(4 * kg + 3) * 68 + o] = w.w;
        }
        __syncthreads();
        #pragma unroll 8
        for (int k = 0; k < 64; k++) {
            float4 w = *(const float4*)&wbuf[k * 68 + 4 * tx];
            #pragma unroll
            for (int r = 0; r < 4; r++) {
                float a = ibuf[(4 * ty + r) * 132 + kc * 64 + k];
                acc2[r][0] += a * w.x; acc2[r][1] += a * w.y;
                acc2[r][2] += a * w.z; acc2[r][3] += a * w.w;
            }
        }
        __syncthreads();
    }

    #pragma unroll
    for (int r = 0; r < 4; r++) {
        int b = blockIdx.x * 32 + 4 * ty + r;
        if (b >= B) continue;
        float4 o;
        o.x = fmaxf(acc2[r][0], 0.f);
        o.y = fmaxf(acc2[r][1], 0.f);
        o.z = fmaxf(acc2[r][2], 0.f);
        o.w = fmaxf(acc2[r][3], 0.f);
        *(float4*)&out[(size_t)b * 2 * EMB + side * EMB + 4 * tx] = o;
    }
}

// ---------------------------------------------------------------------------
extern "C" void kernel_launch(void* const* d_in, const int* in_sizes, int n_in,
                              void* d_out, int out_size)
{
    const float* user_emb = (const float*)d_in[0];
    const float* item_emb = (const float*)d_in[1];
    const float* Wa_u = (const float*)d_in[2];
    const float* Wa_i = (const float*)d_in[3];
    const float* Wfc_u = (const float*)d_in[4];
    const float* Wfc_i = (const float*)d_in[5];
    const float* Ws_u = (const float*)d_in[6];
    const float* bs_u = (const float*)d_in[7];
    const float* Ws_i = (const float*)d_in[8];
    const float* bs_i = (const float*)d_in[9];
    const float* Wn_u = (const float*)d_in[10];
    const float* bn_u = (const float*)d_in[11];
    const float* Wn_i = (const float*)d_in[12];
    const float* bn_i = (const float*)d_in[13];
    const int* u      = (const int*)d_in[14];
    const int* ii     = (const int*)d_in[15];
    const int* src_iu = (const int*)d_in[16];
    const int* dst_iu = (const int*)d_in[17];
    const int* src_ui = (const int*)d_in[18];
    const int* dst_ui = (const int*)d_in[19];
    int B = in_sizes[14];
    int E = in_sizes[16];
    float* out = (float*)d_out;

    {   // K1: mark + zero + dst scores. One warp per (side, b).
        int threads = 256;
        int blocks = (2 * B * 32 + threads - 1) / threads;
        prep_kernel<<<blocks, threads>>>(user_emb, item_emb, Wa_u, Wa_i, u, ii, B);
    }
    {   // K2: fused filtered edge pass, both sides concurrent via gridDim.y.
        int threads = 256;
        int blocks = (E + 8 * 32 - 1) / (8 * 32);
        dim3 g(blocks, 2);
        edge_kernel<<<g, threads>>>(user_emb, item_emb, Wa_u, Wa_i,
                                    src_iu, dst_iu, src_ui, dst_ui, E);
    }
    {   // K3: fully fused MLP (no z round-trip), 4x4 register tiles.
        dim3 g((B + 31) / 32, 2);
        mlp_fused_kernel<<<g, 128>>>(user_emb, item_emb, Ws_u, bs_u, Ws_i, bs_i,
                                     Wn_u, bn_u, Wn_i, bn_i, Wfc_u, Wfc_i,
                                     u, ii, out, B);
    }
}